// round 1
// baseline (speedup 1.0000x reference)
#include <cuda_runtime.h>
#include <cuda_bf16.h>
#include <cstdint>

// Problem constants
#define BB 4
#define TT 2048
#define CC 1024
#define HH 16
#define DD 64
#define MM (BB*TT)   // 8192

// Scratch (device globals: allocation-free)
__device__ float g_q[BB*HH*TT*DD];   // [B,H,T,D]
__device__ float g_k[BB*HH*TT*DD];
__device__ float g_v[BB*HH*TT*DD];
__device__ float g_y[BB*TT*CC];      // [B,T,C] (= [B,T,H,D])

// ---------------------------------------------------------------------------
// Shared GEMM tile body: C[128x128] = A[128xK] * W[128xK]^T  (both K-major)
// 256 threads, 8x8 per-thread microtile with split fragments (conflict-free LDS.128)
// ---------------------------------------------------------------------------
__device__ __forceinline__ void gemm_tile_body(
    const float* __restrict__ A, const float* __restrict__ W,
    int m0, int n0, float acc[8][8],
    float As[8][132], float Bs[8][132])
{
    const int tid  = threadIdx.x;
    const int tx   = tid & 15;
    const int ty   = tid >> 4;
    const int aRow = tid >> 1;
    const int aCol = (tid & 1) << 2;

    const float* Ap = A + (size_t)(m0 + aRow) * CC + aCol;
    const float* Bp = W + (size_t)(n0 + aRow) * CC + aCol;

    #pragma unroll 1
    for (int k0 = 0; k0 < CC; k0 += 8) {
        float4 av = *(const float4*)(Ap + k0);
        float4 bv = *(const float4*)(Bp + k0);
        As[aCol+0][aRow] = av.x; As[aCol+1][aRow] = av.y;
        As[aCol+2][aRow] = av.z; As[aCol+3][aRow] = av.w;
        Bs[aCol+0][aRow] = bv.x; Bs[aCol+1][aRow] = bv.y;
        Bs[aCol+2][aRow] = bv.z; Bs[aCol+3][aRow] = bv.w;
        __syncthreads();
        #pragma unroll
        for (int k = 0; k < 8; k++) {
            float a[8], b[8];
            *(float4*)&a[0] = *(const float4*)&As[k][ty*4];
            *(float4*)&a[4] = *(const float4*)&As[k][64 + ty*4];
            *(float4*)&b[0] = *(const float4*)&Bs[k][tx*4];
            *(float4*)&b[4] = *(const float4*)&Bs[k][64 + tx*4];
            #pragma unroll
            for (int i = 0; i < 8; i++)
                #pragma unroll
                for (int j = 0; j < 8; j++)
                    acc[i][j] += a[i] * b[j];
        }
        __syncthreads();
    }
}

// ---------------------------------------------------------------------------
// Kernel 1: fused QKV projection. grid = (8, 64, 3)
// out layout [B,H,T,D]
// ---------------------------------------------------------------------------
__global__ __launch_bounds__(256)
void qkv_gemm(const float* __restrict__ x,
              const float* __restrict__ Wq,
              const float* __restrict__ Wk,
              const float* __restrict__ Wv)
{
    __shared__ float As[8][132];
    __shared__ float Bs[8][132];

    const float* W = (blockIdx.z == 0) ? Wq : (blockIdx.z == 1) ? Wk : Wv;
    float* dst     = (blockIdx.z == 0) ? g_q : (blockIdx.z == 1) ? g_k : g_v;

    const int m0 = blockIdx.y * 128;
    const int n0 = blockIdx.x * 128;
    float acc[8][8];
    #pragma unroll
    for (int i = 0; i < 8; i++)
        #pragma unroll
        for (int j = 0; j < 8; j++) acc[i][j] = 0.f;

    gemm_tile_body(x, W, m0, n0, acc, As, Bs);

    const int tx = threadIdx.x & 15;
    const int ty = threadIdx.x >> 4;
    #pragma unroll
    for (int i = 0; i < 8; i++) {
        int m  = m0 + ((i >> 2) << 6) + ty*4 + (i & 3);
        int b  = m >> 11;
        int t  = m & (TT - 1);
        #pragma unroll
        for (int g = 0; g < 2; g++) {
            int n = n0 + (g << 6) + tx*4;
            int h = n >> 6;
            int d = n & 63;
            float4 v = make_float4(acc[i][g*4+0], acc[i][g*4+1],
                                   acc[i][g*4+2], acc[i][g*4+3]);
            *(float4*)&dst[(((size_t)(b*HH + h) * TT + t) << 6) + d] = v;
        }
    }
}

// ---------------------------------------------------------------------------
// Kernel 2: fp32 flash attention. grid = (T/64, B*H), 256 threads.
// BR=64 query rows, BC=32 key rows per inner tile. Online softmax.
// Output to g_y in [B,T,C] layout.
// ---------------------------------------------------------------------------
__global__ __launch_bounds__(256)
void flash_kernel()
{
    __shared__ float Qs[64][68];
    __shared__ float Ks[32][68];
    __shared__ float Vs[32][68];
    __shared__ float Ps[64][36];

    const int tid = threadIdx.x;
    const int tx  = tid & 15;
    const int ty  = tid >> 4;
    const int qt  = blockIdx.x;
    const int bh  = blockIdx.y;
    const int b   = bh >> 4;
    const int h   = bh & 15;
    const size_t base = (size_t)bh * TT * DD;

    // Load Q tile (64x64)
    {
        const float4* src = (const float4*)(g_q + base + (size_t)qt * 64 * DD);
        #pragma unroll
        for (int it = 0; it < 4; it++) {
            int f  = tid + it * 256;
            int r  = f >> 4;
            int c4 = f & 15;
            *(float4*)&Qs[r][c4*4] = src[f];
        }
    }

    float o[4][4];
    float mi[4], li[4];
    #pragma unroll
    for (int i = 0; i < 4; i++) {
        mi[i] = -1e30f; li[i] = 0.f;
        #pragma unroll
        for (int j = 0; j < 4; j++) o[i][j] = 0.f;
    }

    const int ntile = 2*qt + 2;   // 32-wide KV tiles up to & including diagonal
    const int qbase = qt * 64;

    for (int jt = 0; jt < ntile; jt++) {
        __syncthreads();  // prior-iter consumers done before overwrite
        // Load K,V tile (32x64 each)
        {
            const float4* ks = (const float4*)(g_k + base + (size_t)jt * 32 * DD);
            const float4* vs = (const float4*)(g_v + base + (size_t)jt * 32 * DD);
            #pragma unroll
            for (int it = 0; it < 2; it++) {
                int f  = tid + it * 256;
                int r  = f >> 4;
                int c4 = f & 15;
                *(float4*)&Ks[r][c4*4] = ks[f];
                *(float4*)&Vs[r][c4*4] = vs[f];
            }
        }
        __syncthreads();

        // S = Q K^T  (64x32), thread owns 4 rows x 2 cols
        float s0[4], s1[4];
        #pragma unroll
        for (int i = 0; i < 4; i++) { s0[i] = 0.f; s1[i] = 0.f; }
        #pragma unroll
        for (int d4 = 0; d4 < 16; d4++) {
            float4 kv0 = *(const float4*)&Ks[tx*2 + 0][d4*4];
            float4 kv1 = *(const float4*)&Ks[tx*2 + 1][d4*4];
            #pragma unroll
            for (int i = 0; i < 4; i++) {
                float4 qv = *(const float4*)&Qs[ty*4 + i][d4*4];
                s0[i] += qv.x*kv0.x + qv.y*kv0.y + qv.z*kv0.z + qv.w*kv0.w;
                s1[i] += qv.x*kv1.x + qv.y*kv1.y + qv.z*kv1.z + qv.w*kv1.w;
            }
        }

        // scale, causal mask, online softmax update
        const int kbase = jt * 32;
        const int kg0 = kbase + tx*2;
        const int kg1 = kg0 + 1;
        #pragma unroll
        for (int i = 0; i < 4; i++) {
            int qg = qbase + ty*4 + i;
            float v0 = s0[i] * 0.125f;
            float v1 = s1[i] * 0.125f;
            if (kg0 > qg) v0 = -1e30f;
            if (kg1 > qg) v1 = -1e30f;
            float rm = fmaxf(v0, v1);
            rm = fmaxf(rm, __shfl_xor_sync(0xffffffffu, rm, 8));
            rm = fmaxf(rm, __shfl_xor_sync(0xffffffffu, rm, 4));
            rm = fmaxf(rm, __shfl_xor_sync(0xffffffffu, rm, 2));
            rm = fmaxf(rm, __shfl_xor_sync(0xffffffffu, rm, 1));
            float mnew = fmaxf(mi[i], rm);
            float corr = __expf(mi[i] - mnew);
            float p0 = __expf(v0 - mnew);
            float p1 = __expf(v1 - mnew);
            float rs = p0 + p1;
            rs += __shfl_xor_sync(0xffffffffu, rs, 8);
            rs += __shfl_xor_sync(0xffffffffu, rs, 4);
            rs += __shfl_xor_sync(0xffffffffu, rs, 2);
            rs += __shfl_xor_sync(0xffffffffu, rs, 1);
            li[i] = li[i]*corr + rs;
            mi[i] = mnew;
            #pragma unroll
            for (int j = 0; j < 4; j++) o[i][j] *= corr;
            Ps[ty*4 + i][tx*2 + 0] = p0;
            Ps[ty*4 + i][tx*2 + 1] = p1;
        }
        __syncthreads();

        // O += P V  (64x64 += 64x32 * 32x64), thread owns 4 rows x 4 cols
        #pragma unroll 4
        for (int c = 0; c < 32; c++) {
            float4 vv = *(const float4*)&Vs[c][tx*4];
            #pragma unroll
            for (int i = 0; i < 4; i++) {
                float pp = Ps[ty*4 + i][c];
                o[i][0] += pp * vv.x;
                o[i][1] += pp * vv.y;
                o[i][2] += pp * vv.z;
                o[i][3] += pp * vv.w;
            }
        }
    }

    // Normalize and write to g_y [B,T,C]
    #pragma unroll
    for (int i = 0; i < 4; i++) {
        float inv = 1.f / li[i];
        int t = qbase + ty*4 + i;
        float4 v = make_float4(o[i][0]*inv, o[i][1]*inv, o[i][2]*inv, o[i][3]*inv);
        *(float4*)&g_y[(((size_t)(b*TT + t)) << 10) + h*64 + tx*4] = v;
    }
}

// ---------------------------------------------------------------------------
// Kernel 3: output projection. grid = (8, 64). out = g_y @ Wp^T, row-major.
// ---------------------------------------------------------------------------
__global__ __launch_bounds__(256)
void proj_gemm(const float* __restrict__ Wp, float* __restrict__ out)
{
    __shared__ float As[8][132];
    __shared__ float Bs[8][132];

    const int m0 = blockIdx.y * 128;
    const int n0 = blockIdx.x * 128;
    float acc[8][8];
    #pragma unroll
    for (int i = 0; i < 8; i++)
        #pragma unroll
        for (int j = 0; j < 8; j++) acc[i][j] = 0.f;

    gemm_tile_body(g_y, Wp, m0, n0, acc, As, Bs);

    const int tx = threadIdx.x & 15;
    const int ty = threadIdx.x >> 4;
    #pragma unroll
    for (int i = 0; i < 8; i++) {
        int m = m0 + ((i >> 2) << 6) + ty*4 + (i & 3);
        #pragma unroll
        for (int g = 0; g < 2; g++) {
            int n = n0 + (g << 6) + tx*4;
            float4 v = make_float4(acc[i][g*4+0], acc[i][g*4+1],
                                   acc[i][g*4+2], acc[i][g*4+3]);
            *(float4*)&out[(size_t)m * CC + n] = v;
        }
    }
}

// ---------------------------------------------------------------------------
extern "C" void kernel_launch(void* const* d_in, const int* in_sizes, int n_in,
                              void* d_out, int out_size)
{
    const float* x  = (const float*)d_in[0];
    const float* Wq = (const float*)d_in[1];
    const float* Wk = (const float*)d_in[2];
    const float* Wv = (const float*)d_in[3];
    const float* Wp = (const float*)d_in[4];
    float* out = (float*)d_out;

    dim3 blk(256);
    qkv_gemm<<<dim3(CC/128, MM/128, 3), blk>>>(x, Wq, Wk, Wv);
    flash_kernel<<<dim3(TT/64, BB*HH), blk>>>();
    proj_gemm<<<dim3(CC/128, MM/128), blk>>>(Wp, out);
}